// round 12
// baseline (speedup 1.0000x reference)
#include <cuda_runtime.h>
#include <cuda_fp16.h>
#include <cstdint>

#define BB 4
#define NN 4096
#define DD 64
#define TM 32
#define TN 64
#define NTILES (NN / TN)
#define DOT_TOL 0.1f
#define L2E 1.44269504f

// ---------------- device scratch (allocation-free) ----------------
__device__ __align__(16) __half g_xhi [BB * NN * DD];   // row-major fp16 (Q & K)
__device__ __align__(16) __half g_xThi[BB * DD * NN];   // transposed fp16 [b][d][n] (V)
__device__ __align__(16) float g_rn [BB * NN];          // 1/||x||
__device__ __align__(16) float g_rnb[BB * NN];          // beta*log2e/||x||

// ---------------- helpers ----------------
__device__ __forceinline__ uint32_t smem_u32(const void* p) {
    uint32_t a;
    asm("{ .reg .u64 t; cvta.to.shared.u64 t, %1; cvt.u32.u64 %0, t; }" : "=r"(a) : "l"(p));
    return a;
}
#define SW(o) ((o) ^ (((o) >> 3) & 0x70))
#define CPA(dst, src) asm volatile("cp.async.cg.shared.global [%0], [%1], 16;" :: "r"(dst), "l"(src))
#define CPC()   asm volatile("cp.async.commit_group;" ::: "memory")
#define CPW0()  asm volatile("cp.async.wait_group 0;" ::: "memory")

__device__ __forceinline__ void ldsm4(uint32_t& r0, uint32_t& r1, uint32_t& r2, uint32_t& r3, uint32_t a) {
    asm volatile("ldmatrix.sync.aligned.m8n8.x4.shared.b16 {%0,%1,%2,%3}, [%4];"
                 : "=r"(r0), "=r"(r1), "=r"(r2), "=r"(r3) : "r"(a));
}
__device__ __forceinline__ void mma16816(float* d, const uint32_t* a, const uint32_t* b) {
    asm volatile("mma.sync.aligned.m16n8k16.row.col.f32.f16.f16.f32 "
                 "{%0,%1,%2,%3}, {%4,%5,%6,%7}, {%8,%9}, {%0,%1,%2,%3};"
                 : "+f"(d[0]), "+f"(d[1]), "+f"(d[2]), "+f"(d[3])
                 : "r"(a[0]), "r"(a[1]), "r"(a[2]), "r"(a[3]), "r"(b[0]), "r"(b[1]));
}
__device__ __forceinline__ uint32_t pack2h(__half a, __half b) {
    return (uint32_t)__half_as_ushort(a) | ((uint32_t)__half_as_ushort(b) << 16);
}
__device__ __forceinline__ float ex2f(float x) {
    float r;
    asm("ex2.approx.f32 %0, %1;" : "=f"(r) : "f"(x));
    return r;
}

// cold-path exact fp32 dot (sign rescue)
__device__ __noinline__ float dot64(const float* __restrict__ a, const float* __restrict__ b) {
    float acc = 0.f;
    #pragma unroll
    for (int i = 0; i < 16; ++i) {
        float4 va = __ldg((const float4*)a + i);
        float4 vb = __ldg((const float4*)b + i);
        acc = fmaf(va.x, vb.x, acc); acc = fmaf(va.y, vb.y, acc);
        acc = fmaf(va.z, vb.z, acc); acc = fmaf(va.w, vb.w, acc);
    }
    return acc;
}

// ---------------- prep ----------------
__global__ __launch_bounds__(256) void prep_kernel(const float* __restrict__ x,
                                                   const float* __restrict__ betap) {
    __shared__ float s[64][68];
    const int row0 = blockIdx.x * 64;
    const int tid = threadIdx.x;

    for (int i = tid; i < 64 * 16; i += 256) {
        int r = i >> 4, c4 = (i & 15) << 2;
        float4 v = *(const float4*)&x[(size_t)(row0 + r) * DD + c4];
        s[r][c4] = v.x; s[r][c4 + 1] = v.y; s[r][c4 + 2] = v.z; s[r][c4 + 3] = v.w;
    }
    __syncthreads();

    const float beta = __ldg(betap);
    if (tid < 64) {
        float acc = 0.f;
        #pragma unroll
        for (int d = 0; d < 64; ++d) acc = fmaf(s[tid][d], s[tid][d], acc);
        float rn = 1.0f / sqrtf(acc);
        g_rn[row0 + tid] = rn;
        g_rnb[row0 + tid] = beta * rn * L2E;   // log2e folded in
    }

    {   // row-major fp16 (Q & K operand)
        int base = tid * 16;
        int r = base >> 6, c = base & 63;
        uint32_t hb[8];
        #pragma unroll
        for (int j = 0; j < 8; ++j)
            hb[j] = pack2h(__float2half_rn(s[r][c + 2 * j]), __float2half_rn(s[r][c + 2 * j + 1]));
        uint4* dh = (uint4*)(g_xhi + (size_t)row0 * DD + base);
        dh[0] = make_uint4(hb[0], hb[1], hb[2], hb[3]);
        dh[1] = make_uint4(hb[4], hb[5], hb[6], hb[7]);
    }
    {   // transposed fp16 (V operand)
        int d = tid >> 2, j0 = (tid & 3) * 16;
        int b = row0 / NN, n0 = row0 % NN;
        uint32_t hb[8];
        #pragma unroll
        for (int j = 0; j < 8; ++j)
            hb[j] = pack2h(__float2half_rn(s[j0 + 2 * j][d]), __float2half_rn(s[j0 + 2 * j + 1][d]));
        size_t off = (size_t)(b * DD + d) * NN + n0 + j0;
        uint4* dh = (uint4*)(g_xThi + off);
        dh[0] = make_uint4(hb[0], hb[1], hb[2], hb[3]);
        dh[1] = make_uint4(hb[4], hb[5], hb[6], hb[7]);
    }
}

// ---------------- smem layout ----------------
// Q: 32x128B = 4K; 2 stages x (K 8K | Vhi 8K | adj 32x272B)
#define OFF_Q       0
#define OFF_ST      4096
#define OFF_VHI     8192                       // within a stage
#define OFF_ADJ     16384
#define ADJ_PITCH   272
#define STAGE_BYTES (16384 + 32 * ADJ_PITCH)   // 25088
#define SMEM_TOTAL  (4096 + 2 * STAGE_BYTES)   // 54272

__device__ __forceinline__ void load_stage(uint32_t stbase, int tid, int b, int q0, int k0,
                                           const float* __restrict__ adj) {
    const __half* kh = g_xhi + ((size_t)b * NN + k0) * DD;
    const __half* vh = g_xThi + (size_t)b * DD * NN + k0;
    #pragma unroll
    for (int it = 0; it < 4; ++it) {
        int m = tid + it * 256;
        int buf = m >> 9, idx = m & 511, r = idx >> 3, c = idx & 7;
        uint32_t dst = stbase + buf * 8192 + SW(r * 128 + c * 16);
        const __half* src = buf ? (vh + (size_t)r * NN + c * 8) : (kh + r * 64 + c * 8);
        CPA(dst, src);
    }
    // adj tile: 32 q-rows x 64 fp32
    const float* ab = adj + ((size_t)b * NN + q0) * NN + k0;
    #pragma unroll
    for (int it = 0; it < 2; ++it) {
        int m = tid + it * 256;            // 0..511
        int r = m >> 4, c = m & 15;
        CPA(stbase + OFF_ADJ + r * ADJ_PITCH + c * 16, ab + (size_t)r * NN + c * 4);
    }
}

// ---------------- main kernel: TM=32, 8 warps, 3 CTAs/SM ----------------
__global__ __launch_bounds__(256, 3)
void attn_mma(const float* __restrict__ x,
              const float* __restrict__ adj,
              const float* __restrict__ betap,
              float* __restrict__ out) {
    extern __shared__ char smem[];
    const uint32_t sb = smem_u32(smem);
    const int tid = threadIdx.x;
    const int wid = tid >> 5, lane = tid & 31;
    const int qr = wid >> 2;          // query rows 16*qr..16*qr+15 (0..1)
    const int h  = wid & 3;           // key quarter: keys 16h..16h+15
    const int g = lane >> 2, t = lane & 3;
    const int b = blockIdx.y, q0 = blockIdx.x * TM;
    const size_t bNN = (size_t)b * NN;

    const int lm = lane >> 3, li = lane & 7;
    const uint32_t b_row = ((lm >> 1) << 3) + li;
    const uint32_t b_kb  = (uint32_t)(lm & 1) << 4;
    const uint32_t a_row = ((uint32_t)(lm & 1) << 3) + li + qr * 16;
    const uint32_t a_kb  = (uint32_t)(lm >> 1) << 4;

    // prologue: Q + tile0
    {
        const __half* qh = g_xhi + (bNN + q0) * DD;
        int r = tid >> 3, c = tid & 7;   // 256 chunks = 32 rows x 8
        CPA(sb + OFF_Q + SW(r * 128 + c * 16), qh + r * 64 + c * 8);
        load_stage(sb + OFF_ST, tid, b, q0, 0, adj);
        CPC();
    }

    const float beta = __ldg(betap);
    const float C2 = (beta + 10.0f) * L2E;
    const float A2 = 10.0f * L2E;
    const int qrow = q0 + qr * 16 + g;
    const float rq0 = g_rn[bNN + qrow];
    const float rq1 = g_rn[bNN + qrow + 8];
    const float* xb  = x + bNN * DD;
    const float* xq0 = xb + (size_t)qrow * DD;
    const float* xq1 = xq0 + 8 * DD;
    const int adj_off = OFF_ADJ + (qr * 16 + g) * ADJ_PITCH + (16 * h + 2 * t) * 4;

    float o[8][4];
    #pragma unroll
    for (int j = 0; j < 8; ++j)
        { o[j][0] = 0.f; o[j][1] = 0.f; o[j][2] = 0.f; o[j][3] = 0.f; }
    float lsum0 = 0.f, lsum1 = 0.f;

    for (int tt = 0; tt < NTILES; ++tt) {
        const int k0 = tt * TN;
        CPW0();
        __syncthreads();
        if (tt + 1 < NTILES) {
            load_stage(sb + OFF_ST + ((tt + 1) & 1) * STAGE_BYTES, tid, b, q0, k0 + TN, adj);
            CPC();
        }
        const int stoff = OFF_ST + (tt & 1) * STAGE_BYTES;
        const uint32_t stb = sb + stoff;
        const float* sa0 = (const float*)(smem + stoff + adj_off);           // row g
        const float* sa1 = (const float*)((const char*)sa0 + 8 * ADJ_PITCH); // row g+8

        // ---- S = Q * K (single-term fp16, fp32 accum), 16x16 per warp ----
        float s[2][4];
        s[0][0] = s[0][1] = s[0][2] = s[0][3] = 0.f;
        s[1][0] = s[1][1] = s[1][2] = s[1][3] = 0.f;

        #pragma unroll
        for (int ks = 0; ks < 4; ++ks) {
            uint32_t qf[4], bf[2][2];
            ldsm4(qf[0], qf[1], qf[2], qf[3], sb + OFF_Q + SW(a_row * 128 + ks * 32 + a_kb));
            ldsm4(bf[0][0], bf[0][1], bf[1][0], bf[1][1],
                  stb + SW((16 * h + b_row) * 128 + ks * 32 + b_kb));
            mma16816(s[0], qf, bf[0]);
            mma16816(s[1], qf, bf[1]);
        }

        // ---- logits -> ex2 -> pack P ----
        uint32_t ahi[4];
        {
            const float* rnbp = g_rnb + bNN + k0 + 16 * h + 2 * t;
            #pragma unroll
            for (int j = 0; j < 2; ++j) {
                float2 av0 = *(const float2*)(sa0 + 8 * j);
                float2 av1 = *(const float2*)(sa1 + 8 * j);
                {   // cold fp32 sign rescue
                    bool n0 = (av0.x > 0.5f) && (fabsf(s[j][0]) < DOT_TOL);
                    bool n1 = (av0.y > 0.5f) && (fabsf(s[j][1]) < DOT_TOL);
                    bool n2 = (av1.x > 0.5f) && (fabsf(s[j][2]) < DOT_TOL);
                    bool n3 = (av1.y > 0.5f) && (fabsf(s[j][3]) < DOT_TOL);
                    if (n0 | n1 | n2 | n3) {
                        const int kk = k0 + 16 * h + 8 * j + 2 * t;
                        if (n0) s[j][0] = dot64(xq0, xb + (size_t)kk * DD);
                        if (n1) s[j][1] = dot64(xq0, xb + (size_t)(kk + 1) * DD);
                        if (n2) s[j][2] = dot64(xq1, xb + (size_t)kk * DD);
                        if (n3) s[j][3] = dot64(xq1, xb + (size_t)(kk + 1) * DD);
                    }
                }
                float2 rk = __ldg((const float2*)(rnbp + 8 * j));
                float lg0 = (s[j][0] < 0.f) ? -1e30f : fmaf(A2, av0.x, fmaf(s[j][0], rq0 * rk.x, -C2));
                float lg1 = (s[j][1] < 0.f) ? -1e30f : fmaf(A2, av0.y, fmaf(s[j][1], rq0 * rk.y, -C2));
                float lg2 = (s[j][2] < 0.f) ? -1e30f : fmaf(A2, av1.x, fmaf(s[j][2], rq1 * rk.x, -C2));
                float lg3 = (s[j][3] < 0.f) ? -1e30f : fmaf(A2, av1.y, fmaf(s[j][3], rq1 * rk.y, -C2));
                float p0 = ex2f(lg0), p1 = ex2f(lg1), p2 = ex2f(lg2), p3 = ex2f(lg3);
                lsum0 += p0 + p1; lsum1 += p2 + p3;
                uint32_t h01, h23;
                asm("cvt.rn.f16x2.f32 %0, %1, %2;" : "=r"(h01) : "f"(p1), "f"(p0));
                asm("cvt.rn.f16x2.f32 %0, %1, %2;" : "=r"(h23) : "f"(p3), "f"(p2));
                ahi[2 * j]     = h01;    // rows g,   k-lo/hi of this j
                ahi[2 * j + 1] = h23;    // rows g+8
            }
        }

        // ---- O += P * Vhi over this warp's 16 keys, all 64 dims ----
        #pragma unroll
        for (int nb = 0; nb < 4; ++nb) {
            uint32_t bf[2][2];
            ldsm4(bf[0][0], bf[0][1], bf[1][0], bf[1][1],
                  stb + OFF_VHI + SW((nb * 16 + b_row) * 128 + h * 32 + b_kb));
            mma16816(o[2 * nb],     ahi, bf[0]);
            mma16816(o[2 * nb + 1], ahi, bf[1]);
        }
    }

    // ---- epilogue: combine 4 key-quarters via smem, normalize, store ----
    lsum0 += __shfl_xor_sync(0xffffffffu, lsum0, 1);
    lsum0 += __shfl_xor_sync(0xffffffffu, lsum0, 2);
    lsum1 += __shfl_xor_sync(0xffffffffu, lsum1, 1);
    lsum1 += __shfl_xor_sync(0xffffffffu, lsum1, 2);

    __syncthreads();   // all stage reads done; reuse stage region
    float* obuf = (float*)(smem + OFF_ST);              // 3 partials x 32x64
    float* lbuf = (float*)(smem + OFF_ST + 24576);      // [32][4]
    const int row = qr * 16 + g;                         // 0..15 (+8 sibling)

    if (h != 0) {
        float* base = obuf + (h - 1) * 2048;
        #pragma unroll
        for (int j = 0; j < 8; ++j) {
            *(float2*)(base + row * 64 + 8 * j + 2 * t)       = make_float2(o[j][0], o[j][1]);
            *(float2*)(base + (row + 8) * 64 + 8 * j + 2 * t) = make_float2(o[j][2], o[j][3]);
        }
        if (t == 0) { lbuf[row * 4 + h] = lsum0; lbuf[(row + 8) * 4 + h] = lsum1; }
    }
    __syncthreads();
    if (h == 0) {
        lsum0 += lbuf[row * 4 + 1] + lbuf[row * 4 + 2] + lbuf[row * 4 + 3];
        lsum1 += lbuf[(row + 8) * 4 + 1] + lbuf[(row + 8) * 4 + 2] + lbuf[(row + 8) * 4 + 3];
        const float inv0 = 1.0f / lsum0;
        const float inv1 = 1.0f / lsum1;
        float* o0 = out + (bNN + qrow) * DD + 2 * t;
        float* o1 = o0 + 8 * DD;
        #pragma unroll
        for (int j = 0; j < 8; ++j) {
            int c0 = row * 64 + 8 * j + 2 * t, c1 = (row + 8) * 64 + 8 * j + 2 * t;
            float2 p0 = *(float2*)(obuf + c0);
            float2 p1 = *(float2*)(obuf + 2048 + c0);
            float2 p2 = *(float2*)(obuf + 4096 + c0);
            float2 q0v = *(float2*)(obuf + c1);
            float2 q1v = *(float2*)(obuf + 2048 + c1);
            float2 q2v = *(float2*)(obuf + 4096 + c1);
            *(float2*)(o0 + 8 * j) = make_float2((o[j][0] + p0.x + p1.x + p2.x) * inv0,
                                                 (o[j][1] + p0.y + p1.y + p2.y) * inv0);
            *(float2*)(o1 + 8 * j) = make_float2((o[j][2] + q0v.x + q1v.x + q2v.x) * inv1,
                                                 (o[j][3] + q0v.y + q1v.y + q2v.y) * inv1);
        }
    }
}

// ---------------------------------------------------------------------------
extern "C" void kernel_launch(void* const* d_in, const int* in_sizes, int n_in,
                              void* d_out, int out_size) {
    (void)in_sizes; (void)n_in; (void)out_size;
    const float* x    = (const float*)d_in[0];
    const float* adj  = (const float*)d_in[1];
    const float* beta = (const float*)d_in[2];
    float* out = (float*)d_out;

    prep_kernel<<<BB * NN / 64, 256>>>(x, beta);

    cudaFuncSetAttribute(attn_mma, cudaFuncAttributeMaxDynamicSharedMemorySize, SMEM_TOTAL);
    dim3 grid(NN / TM, BB);
    attn_mma<<<grid, 256, SMEM_TOTAL>>>(x, adj, beta, out);
}

// round 14
// speedup vs baseline: 1.2369x; 1.2369x over previous
#include <cuda_runtime.h>
#include <cuda_fp16.h>
#include <cstdint>

#define BB 4
#define NN 4096
#define DD 64
#define TM 64
#define TN 64
#define NTILES (NN / TN)
#define DOT_TOL 0.1f
#define L2E 1.44269504f

// ---------------- device scratch (allocation-free) ----------------
__device__ __align__(16) __half g_xhi [BB * NN * DD];   // row-major fp16 (Q & K)
__device__ __align__(16) __half g_xThi[BB * DD * NN];   // transposed fp16 [b][d][n] (V)
__device__ __align__(16) float g_rn [BB * NN];          // 1/||x||
__device__ __align__(16) float g_rnb[BB * NN];          // beta*log2e/||x||

// ---------------- helpers ----------------
__device__ __forceinline__ uint32_t smem_u32(const void* p) {
    uint32_t a;
    asm("{ .reg .u64 t; cvta.to.shared.u64 t, %1; cvt.u32.u64 %0, t; }" : "=r"(a) : "l"(p));
    return a;
}
#define SW(o) ((o) ^ (((o) >> 3) & 0x70))
#define CPA(dst, src) asm volatile("cp.async.cg.shared.global [%0], [%1], 16;" :: "r"(dst), "l"(src))
#define CPC()   asm volatile("cp.async.commit_group;" ::: "memory")
#define CPW0()  asm volatile("cp.async.wait_group 0;" ::: "memory")
#define CPW1()  asm volatile("cp.async.wait_group 1;" ::: "memory")

__device__ __forceinline__ void ldsm4(uint32_t& r0, uint32_t& r1, uint32_t& r2, uint32_t& r3, uint32_t a) {
    asm volatile("ldmatrix.sync.aligned.m8n8.x4.shared.b16 {%0,%1,%2,%3}, [%4];"
                 : "=r"(r0), "=r"(r1), "=r"(r2), "=r"(r3) : "r"(a));
}
__device__ __forceinline__ void mma16816(float* d, const uint32_t* a, const uint32_t* b) {
    asm volatile("mma.sync.aligned.m16n8k16.row.col.f32.f16.f16.f32 "
                 "{%0,%1,%2,%3}, {%4,%5,%6,%7}, {%8,%9}, {%0,%1,%2,%3};"
                 : "+f"(d[0]), "+f"(d[1]), "+f"(d[2]), "+f"(d[3])
                 : "r"(a[0]), "r"(a[1]), "r"(a[2]), "r"(a[3]), "r"(b[0]), "r"(b[1]));
}
__device__ __forceinline__ uint32_t pack2h(__half a, __half b) {
    return (uint32_t)__half_as_ushort(a) | ((uint32_t)__half_as_ushort(b) << 16);
}
__device__ __forceinline__ float ex2f(float x) {
    float r;
    asm("ex2.approx.f32 %0, %1;" : "=f"(r) : "f"(x));
    return r;
}

// cold-path exact fp32 dot (sign rescue)
__device__ __noinline__ float dot64(const float* __restrict__ a, const float* __restrict__ b) {
    float acc = 0.f;
    #pragma unroll
    for (int i = 0; i < 16; ++i) {
        float4 va = __ldg((const float4*)a + i);
        float4 vb = __ldg((const float4*)b + i);
        acc = fmaf(va.x, vb.x, acc); acc = fmaf(va.y, vb.y, acc);
        acc = fmaf(va.z, vb.z, acc); acc = fmaf(va.w, vb.w, acc);
    }
    return acc;
}

// ---------------- prep ----------------
__global__ __launch_bounds__(256) void prep_kernel(const float* __restrict__ x,
                                                   const float* __restrict__ betap) {
    __shared__ float s[64][68];
    const int row0 = blockIdx.x * 64;
    const int tid = threadIdx.x;

    for (int i = tid; i < 64 * 16; i += 256) {
        int r = i >> 4, c4 = (i & 15) << 2;
        float4 v = *(const float4*)&x[(size_t)(row0 + r) * DD + c4];
        s[r][c4] = v.x; s[r][c4 + 1] = v.y; s[r][c4 + 2] = v.z; s[r][c4 + 3] = v.w;
    }
    __syncthreads();

    const float beta = __ldg(betap);
    if (tid < 64) {
        float acc = 0.f;
        #pragma unroll
        for (int d = 0; d < 64; ++d) acc = fmaf(s[tid][d], s[tid][d], acc);
        float rn = 1.0f / sqrtf(acc);
        g_rn[row0 + tid] = rn;
        g_rnb[row0 + tid] = beta * rn * L2E;
    }

    {   // row-major fp16 (Q & K operand)
        int base = tid * 16;
        int r = base >> 6, c = base & 63;
        uint32_t hb[8];
        #pragma unroll
        for (int j = 0; j < 8; ++j)
            hb[j] = pack2h(__float2half_rn(s[r][c + 2 * j]), __float2half_rn(s[r][c + 2 * j + 1]));
        uint4* dh = (uint4*)(g_xhi + (size_t)row0 * DD + base);
        dh[0] = make_uint4(hb[0], hb[1], hb[2], hb[3]);
        dh[1] = make_uint4(hb[4], hb[5], hb[6], hb[7]);
    }
    {   // transposed fp16 (V operand)
        int d = tid >> 2, j0 = (tid & 3) * 16;
        int b = row0 / NN, n0 = row0 % NN;
        uint32_t hb[8];
        #pragma unroll
        for (int j = 0; j < 8; ++j)
            hb[j] = pack2h(__float2half_rn(s[j0 + 2 * j][d]), __float2half_rn(s[j0 + 2 * j + 1][d]));
        size_t off = (size_t)(b * DD + d) * NN + n0 + j0;
        uint4* dh = (uint4*)(g_xThi + off);
        dh[0] = make_uint4(hb[0], hb[1], hb[2], hb[3]);
        dh[1] = make_uint4(hb[4], hb[5], hb[6], hb[7]);
    }
}

// ---------------- smem layout ----------------
// Q: 64x128B = 8K; 3 stages x (K 8K | Vhi 8K | adj 64x272B = 17408)
#define OFF_Q       0
#define OFF_ST      8192
#define OFF_VHI     8192                       // within a stage
#define OFF_ADJ     16384
#define ADJ_PITCH   272
#define STAGE_BYTES (16384 + 64 * ADJ_PITCH)   // 33792
#define SMEM_TOTAL  (8192 + 3 * STAGE_BYTES)   // 109568

__device__ __forceinline__ void load_stage(uint32_t stbase, int tid, int b, int q0, int k0,
                                           const float* __restrict__ adj) {
    const __half* kh = g_xhi + ((size_t)b * NN + k0) * DD;
    const __half* vh = g_xThi + (size_t)b * DD * NN + k0;
    #pragma unroll
    for (int it = 0; it < 4; ++it) {
        int m = tid + it * 256;
        int buf = m >> 9, idx = m & 511, r = idx >> 3, c = idx & 7;
        uint32_t dst = stbase + buf * 8192 + SW(r * 128 + c * 16);
        const __half* src = buf ? (vh + (size_t)r * NN + c * 8) : (kh + r * 64 + c * 8);
        CPA(dst, src);
    }
    // adj tile: 64 q-rows x 64 fp32
    const float* ab = adj + ((size_t)b * NN + q0) * NN + k0;
    #pragma unroll
    for (int it = 0; it < 4; ++it) {
        int m = tid + it * 256;            // 0..1023
        int r = m >> 4, c = m & 15;
        CPA(stbase + OFF_ADJ + r * ADJ_PITCH + c * 16, ab + (size_t)r * NN + c * 4);
    }
}

// ---------------- main kernel: TM=64, 8 warps (16q x 32k), 2 CTAs/SM ----------------
__global__ __launch_bounds__(256, 2)
void attn_mma(const float* __restrict__ x,
              const float* __restrict__ adj,
              const float* __restrict__ betap,
              float* __restrict__ out) {
    extern __shared__ char smem[];
    const uint32_t sb = smem_u32(smem);
    const int tid = threadIdx.x;
    const int wid = tid >> 5, lane = tid & 31;
    const int qr = wid >> 1;          // query rows 16*qr..16*qr+15
    const int h  = wid & 1;           // key half: keys 32h..32h+31
    const int g = lane >> 2, t = lane & 3;
    const int b = blockIdx.y, q0 = blockIdx.x * TM;
    const size_t bNN = (size_t)b * NN;

    const int lm = lane >> 3, li = lane & 7;
    const uint32_t b_row = ((lm >> 1) << 3) + li;
    const uint32_t b_kb  = (uint32_t)(lm & 1) << 4;
    const uint32_t a_row = ((uint32_t)(lm & 1) << 3) + li + qr * 16;
    const uint32_t a_kb  = (uint32_t)(lm >> 1) << 4;

    // prologue: Q + stage0 in group0, stage1 in group1
    {
        const __half* qh = g_xhi + (bNN + q0) * DD;
        #pragma unroll
        for (int it = 0; it < 2; ++it) {
            int m = tid + it * 256;
            int r = m >> 3, c = m & 7;
            CPA(sb + OFF_Q + SW(r * 128 + c * 16), qh + r * 64 + c * 8);
        }
        load_stage(sb + OFF_ST, tid, b, q0, 0, adj);
        CPC();
        load_stage(sb + OFF_ST + STAGE_BYTES, tid, b, q0, TN, adj);
        CPC();
    }

    const float beta = __ldg(betap);
    const float C2 = (beta + 10.0f) * L2E;
    const float A2 = 10.0f * L2E;
    const int qrow = q0 + qr * 16 + g;
    const float rq0 = g_rn[bNN + qrow];
    const float rq1 = g_rn[bNN + qrow + 8];
    const float* xb  = x + bNN * DD;
    const float* xq0 = xb + (size_t)qrow * DD;
    const float* xq1 = xq0 + 8 * DD;
    const int adj_off = OFF_ADJ + (qr * 16 + g) * ADJ_PITCH + (32 * h + 2 * t) * 4;

    uint32_t qhiF[4][4];
    float o[8][4];
    #pragma unroll
    for (int j = 0; j < 8; ++j)
        { o[j][0] = 0.f; o[j][1] = 0.f; o[j][2] = 0.f; o[j][3] = 0.f; }
    float lsum0 = 0.f, lsum1 = 0.f;

    int stc = 0;   // consume stage index

    for (int tt = 0; tt < NTILES; ++tt) {
        const int k0 = tt * TN;
        if (tt + 1 < NTILES) { CPW1(); } else { CPW0(); }   // stage tt ready
        __syncthreads();
        if (tt + 2 < NTILES) {
            int sti = stc + 2; if (sti >= 3) sti -= 3;
            load_stage(sb + OFF_ST + sti * STAGE_BYTES, tid, b, q0, k0 + 2 * TN, adj);
            CPC();
        }
        if (tt == 0) {
            #pragma unroll
            for (int ks = 0; ks < 4; ++ks) {
                uint32_t ad = sb + OFF_Q + SW(a_row * 128 + ks * 32 + a_kb);
                ldsm4(qhiF[ks][0], qhiF[ks][1], qhiF[ks][2], qhiF[ks][3], ad);
            }
        }
        const int stoff = OFF_ST + stc * STAGE_BYTES;
        const uint32_t stb = sb + stoff;
        const float* sa0 = (const float*)(smem + stoff + adj_off);           // row g
        const float* sa1 = (const float*)((const char*)sa0 + 8 * ADJ_PITCH); // row g+8

        // ---- S = Q * K (single-term fp16, fp32 accum), 16x32 per warp ----
        float s[4][4];
        #pragma unroll
        for (int j = 0; j < 4; ++j)
            { s[j][0] = 0.f; s[j][1] = 0.f; s[j][2] = 0.f; s[j][3] = 0.f; }

        #pragma unroll
        for (int ks = 0; ks < 4; ++ks) {
            uint32_t bf[4][2];
            #pragma unroll
            for (int nb = 0; nb < 2; ++nb) {
                uint32_t ad = stb + SW((32 * h + nb * 16 + b_row) * 128 + ks * 32 + b_kb);
                ldsm4(bf[2 * nb][0], bf[2 * nb][1], bf[2 * nb + 1][0], bf[2 * nb + 1][1], ad);
            }
            #pragma unroll
            for (int j = 0; j < 4; ++j) mma16816(s[j], qhiF[ks], bf[j]);
        }

        // ---- logits -> ex2 -> pack P ----
        uint32_t ahi[2][4];
        {
            const float* rnbp = g_rnb + bNN + k0 + 32 * h + 2 * t;
            #pragma unroll
            for (int j = 0; j < 4; ++j) {
                float2 av0 = *(const float2*)(sa0 + 8 * j);
                float2 av1 = *(const float2*)(sa1 + 8 * j);
                {   // cold fp32 sign rescue
                    bool n0 = (av0.x > 0.5f) && (fabsf(s[j][0]) < DOT_TOL);
                    bool n1 = (av0.y > 0.5f) && (fabsf(s[j][1]) < DOT_TOL);
                    bool n2 = (av1.x > 0.5f) && (fabsf(s[j][2]) < DOT_TOL);
                    bool n3 = (av1.y > 0.5f) && (fabsf(s[j][3]) < DOT_TOL);
                    if (n0 | n1 | n2 | n3) {
                        const int kk = k0 + 32 * h + 8 * j + 2 * t;
                        if (n0) s[j][0] = dot64(xq0, xb + (size_t)kk * DD);
                        if (n1) s[j][1] = dot64(xq0, xb + (size_t)(kk + 1) * DD);
                        if (n2) s[j][2] = dot64(xq1, xb + (size_t)kk * DD);
                        if (n3) s[j][3] = dot64(xq1, xb + (size_t)(kk + 1) * DD);
                    }
                }
                float2 rk = __ldg((const float2*)(rnbp + 8 * j));
                float lg0 = (s[j][0] < 0.f) ? -1e30f : fmaf(A2, av0.x, fmaf(s[j][0], rq0 * rk.x, -C2));
                float lg1 = (s[j][1] < 0.f) ? -1e30f : fmaf(A2, av0.y, fmaf(s[j][1], rq0 * rk.y, -C2));
                float lg2 = (s[j][2] < 0.f) ? -1e30f : fmaf(A2, av1.x, fmaf(s[j][2], rq1 * rk.x, -C2));
                float lg3 = (s[j][3] < 0.f) ? -1e30f : fmaf(A2, av1.y, fmaf(s[j][3], rq1 * rk.y, -C2));
                float p0 = ex2f(lg0), p1 = ex2f(lg1), p2 = ex2f(lg2), p3 = ex2f(lg3);
                lsum0 += p0 + p1; lsum1 += p2 + p3;
                uint32_t h01, h23;
                asm("cvt.rn.f16x2.f32 %0, %1, %2;" : "=r"(h01) : "f"(p1), "f"(p0));
                asm("cvt.rn.f16x2.f32 %0, %1, %2;" : "=r"(h23) : "f"(p3), "f"(p2));
                int cc = j >> 1, hp = (j & 1) << 1;
                ahi[cc][hp] = h01; ahi[cc][hp + 1] = h23;
            }
        }

        // ---- O += P * Vhi over this warp's 32 keys, all 64 dims ----
        #pragma unroll
        for (int cl = 0; cl < 2; ++cl) {
            const int c = 2 * h + cl;
            uint32_t bf[8][2];
            #pragma unroll
            for (int nb = 0; nb < 4; ++nb) {
                uint32_t ad = stb + OFF_VHI + SW((nb * 16 + b_row) * 128 + c * 32 + b_kb);
                ldsm4(bf[2 * nb][0], bf[2 * nb][1], bf[2 * nb + 1][0], bf[2 * nb + 1][1], ad);
            }
            #pragma unroll
            for (int j = 0; j < 8; ++j) mma16816(o[j], ahi[cl], bf[j]);
        }

        if (++stc == 3) stc = 0;
    }

    // ---- epilogue: combine key halves via smem, normalize, store ----
    lsum0 += __shfl_xor_sync(0xffffffffu, lsum0, 1);
    lsum0 += __shfl_xor_sync(0xffffffffu, lsum0, 2);
    lsum1 += __shfl_xor_sync(0xffffffffu, lsum1, 1);
    lsum1 += __shfl_xor_sync(0xffffffffu, lsum1, 2);

    __syncthreads();   // all stage reads done; reuse stage region
    float* obuf = (float*)(smem + OFF_ST);            // [qr][16][64]
    float* lbuf = (float*)(smem + OFF_ST + 16384);    // [64]

    if (h == 1) {
        float* base = obuf + qr * 1024;
        #pragma unroll
        for (int j = 0; j < 8; ++j) {
            *(float2*)(base + g * 64 + 8 * j + 2 * t)       = make_float2(o[j][0], o[j][1]);
            *(float2*)(base + (g + 8) * 64 + 8 * j + 2 * t) = make_float2(o[j][2], o[j][3]);
        }
        if (t == 0) { lbuf[qr * 16 + g] = lsum0; lbuf[qr * 16 + g + 8] = lsum1; }
    }
    __syncthreads();
    if (h == 0) {
        float* base = obuf + qr * 1024;
        lsum0 += lbuf[qr * 16 + g];
        lsum1 += lbuf[qr * 16 + g + 8];
        const float inv0 = 1.0f / lsum0;
        const float inv1 = 1.0f / lsum1;
        float* o0 = out + (bNN + qrow) * DD + 2 * t;
        float* o1 = o0 + 8 * DD;
        #pragma unroll
        for (int j = 0; j < 8; ++j) {
            float2 p0 = *(float2*)(base + g * 64 + 8 * j + 2 * t);
            float2 p1 = *(float2*)(base + (g + 8) * 64 + 8 * j + 2 * t);
            *(float2*)(o0 + 8 * j) = make_float2((o[j][0] + p0.x) * inv0, (o[j][1] + p0.y) * inv0);
            *(float2*)(o1 + 8 * j) = make_float2((o[j][2] + p1.x) * inv1, (o[j][3] + p1.y) * inv1);
        }
    }
}

// ---------------------------------------------------------------------------
extern "C" void kernel_launch(void* const* d_in, const int* in_sizes, int n_in,
                              void* d_out, int out_size) {
    (void)in_sizes; (void)n_in; (void)out_size;
    const float* x    = (const float*)d_in[0];
    const float* adj  = (const float*)d_in[1];
    const float* beta = (const float*)d_in[2];
    float* out = (float*)d_out;

    prep_kernel<<<BB * NN / 64, 256>>>(x, beta);

    cudaFuncSetAttribute(attn_mma, cudaFuncAttributeMaxDynamicSharedMemorySize, SMEM_TOTAL);
    dim3 grid(NN / TM, BB);
    attn_mma<<<grid, 256, SMEM_TOTAL>>>(x, adj, beta, out);
}